// round 5
// baseline (speedup 1.0000x reference)
#include <cuda_runtime.h>
#include <cuda_bf16.h>
#include <cstdint>

// Problem constants (fixed by the dataset)
#define NB   2048
#define NC   9605
#define TPB  256
#define TOPK 10

#define CLIP      0.05f
#define EPS_F     1e-8f
#define ALPHA1    2.0f
#define ALPHA_OTH 0.5f

__device__ float        g_row_sums[NB];
__device__ unsigned int g_count = 0;

__device__ __forceinline__ bool beats(float v, int i, float V, int I) {
    // jax.lax.top_k order: larger value first; ties -> lower index first
    return (v > V) || (v == V && i < I);
}

// base * w for a single element, branch-free, single LG2 (select arg before log)
__device__ __forceinline__ float elem_term(float xv, float yv) {
    float e  = __expf(-xv);
    float p  = __fdividef(1.0f, 1.0f + e);          // sigmoid
    float xn = fminf(1.0f - p + CLIP, 1.0f);        // clipped negative prob
    bool  pos = (yv != 0.0f);
    float arg  = pos ? p : xn;
    float onem = 1.0f - arg;                         // (1-p) or (1-xn)
    float o2   = onem * onem;
    float w    = pos ? onem : (o2 * o2);             // gamma 1 vs 4
    return __logf(fmaxf(arg, EPS_F)) * w;
}

__device__ __forceinline__ void try_insert(float v, int i,
                                           float (&tv)[TOPK], int (&ti)[TOPK]) {
    if (beats(v, i, tv[TOPK-1], ti[TOPK-1])) {
        tv[TOPK-1] = v; ti[TOPK-1] = i;
        #pragma unroll
        for (int k = TOPK - 1; k > 0; k--) {
            if (beats(tv[k], ti[k], tv[k-1], ti[k-1])) {
                float fv = tv[k]; tv[k] = tv[k-1]; tv[k-1] = fv;
                int   iv = ti[k]; ti[k] = ti[k-1]; ti[k-1] = iv;
            }
        }
    }
}

__global__ void __launch_bounds__(TPB)
fused_kernel(const float* __restrict__ x, const float* __restrict__ y,
             const int* __restrict__ compost, int n_compost,
             const int* __restrict__ recycle, int n_recycle,
             const int* __restrict__ donate,  int n_donate,
             const int* __restrict__ wl_map,
             float* __restrict__ out)
{
    const int row = blockIdx.x;
    const int tid = threadIdx.x;
    const float* __restrict__ xr = x + (long long)row * NC;
    const float* __restrict__ yr = y + (long long)row * NC;

    __shared__ int   s_has[3];
    __shared__ float s_v[TPB * TOPK];
    __shared__ int   s_i[TPB * TOPK];
    __shared__ float s_sum[TPB];
    __shared__ int   s_islast;

    if (tid < 3) s_has[tid] = 0;
    __syncthreads();

    // ---- per-sample ground-truth whitelist flags (benign-race stores) ----
    for (int k = tid; k < n_compost; k += TPB)
        if (yr[compost[k]] != 0.0f) s_has[0] = 1;
    for (int k = tid; k < n_recycle; k += TPB)
        if (yr[recycle[k]] != 0.0f) s_has[1] = 1;
    for (int k = tid; k < n_donate; k += TPB)
        if (yr[donate[k]] != 0.0f) s_has[2] = 1;

    // Row alignment: (row*NC) % 4 == row % 4, so `lead` scalars make the body
    // 16B-aligned for float4 (x and y share NC, hence the same lead).
    const int lead = (4 - (row & 3)) & 3;
    const int nb4  = (NC - lead) >> 2;
    const int tail = lead + (nb4 << 2);
    const float4* __restrict__ x4 = (const float4*)(xr + lead);
    const float4* __restrict__ y4 = (const float4*)(yr + lead);

    // ================= Loop 1: branch-free streaming sum =================
    float sum = 0.0f;
    if (tid < lead)       sum += elem_term(xr[tid], yr[tid]);
    for (int q = tid; q < nb4; q += TPB) {
        float4 xv = x4[q];
        float4 yv = y4[q];
        sum += elem_term(xv.x, yv.x);
        sum += elem_term(xv.y, yv.y);
        sum += elem_term(xv.z, yv.z);
        sum += elem_term(xv.w, yv.w);
    }
    for (int j = tail + tid; j < NC; j += TPB)
        sum += elem_term(xr[j], yr[j]);

    // ================= Loop 2: top-10 of x (gated insert) ================
    float tv[TOPK];
    int   ti[TOPK];
    #pragma unroll
    for (int k = 0; k < TOPK; k++) { tv[k] = __int_as_float(0xff800000); ti[k] = 0x7fffffff; }

    if (tid < lead) try_insert(xr[tid], tid, tv, ti);
    for (int q = tid; q < nb4; q += TPB) {
        float4 xv = x4[q];
        float m = fmaxf(fmaxf(xv.x, xv.y), fmaxf(xv.z, xv.w));
        if (m >= tv[TOPK-1]) {                 // cheap reject for the whole quad
            int j = lead + (q << 2);
            try_insert(xv.x, j + 0, tv, ti);
            try_insert(xv.y, j + 1, tv, ti);
            try_insert(xv.z, j + 2, tv, ti);
            try_insert(xv.w, j + 3, tv, ti);
        }
    }
    for (int j = tail + tid; j < NC; j += TPB)
        try_insert(xr[j], j, tv, ti);

    #pragma unroll
    for (int k = 0; k < TOPK; k++) {
        s_v[tid * TOPK + k] = tv[k];
        s_i[tid * TOPK + k] = ti[k];
    }
    s_sum[tid] = sum;
    __syncthreads();

    // ---- tree merge of sorted top-10 lists + tree reduce of sums ----
    for (int stride = TPB / 2; stride >= 1; stride >>= 1) {
        if (tid < stride) {
            const int ai = tid * TOPK;
            const int bi = (tid + stride) * TOPK;
            float mv[TOPK]; int mi[TOPK];
            int a = 0, b = 0;
            #pragma unroll
            for (int k = 0; k < TOPK; k++) {
                float av = s_v[ai + a]; int aidx = s_i[ai + a];
                float bv = s_v[bi + b]; int bidx = s_i[bi + b];
                if (beats(av, aidx, bv, bidx)) { mv[k] = av; mi[k] = aidx; a++; }
                else                            { mv[k] = bv; mi[k] = bidx; b++; }
            }
            #pragma unroll
            for (int k = 0; k < TOPK; k++) { s_v[ai + k] = mv[k]; s_i[ai + k] = mi[k]; }
            s_sum[tid] += s_sum[tid + stride];
        }
        __syncthreads();
    }

    // ---- serial whitelist epilogue on the top-10 (thread 0) ----
    if (tid == 0) {
        bool has1 = s_has[0] != 0, has2 = s_has[1] != 0, has3 = s_has[2] != 0;
        bool gt_only4 = !(has1 || has2 || has3);
        bool found = false;
        float mults[TOPK];
        #pragma unroll
        for (int k = 0; k < TOPK; k++) {
            int j  = s_i[k];
            int wl = wl_map[j];
            bool in_map = wl > 0;
            bool in_gt = ((wl == 1) && has1) || ((wl == 2) && has2) ||
                         ((wl == 3) && has3) || ((wl == 4) && gt_only4);
            float f = 1.0f;
            if (in_map && gt_only4)              f *= ALPHA_OTH;
            if (in_map && !in_gt && !found)      f *= ALPHA1;
            mults[k] = f;
            found = found || (in_map && in_gt);
        }
        float extra = found ? 1.0f : ALPHA1;
        float adj = 0.0f;
        #pragma unroll
        for (int k = 0; k < TOPK; k++) {
            float m = mults[k] * extra;
            if (m != 1.0f) {
                int j = s_i[k];
                adj += elem_term(xr[j], yr[j]) * (m - 1.0f);
            }
        }
        g_row_sums[row] = s_sum[0] + adj;
        __threadfence();
        unsigned int old = atomicAdd(&g_count, 1u);
        s_islast = (old == NB - 1) ? 1 : 0;
    }
    __syncthreads();

    // ---- last CTA folds the 2048 row sums (deterministic fixed order) ----
    if (s_islast) {
        __threadfence();
        float s = 0.0f;
        for (int i = tid; i < NB; i += TPB) s += g_row_sums[i];
        s_sum[tid] = s;
        __syncthreads();
        for (int st = TPB / 2; st >= 1; st >>= 1) {
            if (tid < st) s_sum[tid] += s_sum[tid + st];
            __syncthreads();
        }
        if (tid == 0) {
            out[0] = -s_sum[0];
            g_count = 0;   // reset for next graph replay
        }
    }
}

extern "C" void kernel_launch(void* const* d_in, const int* in_sizes, int n_in,
                              void* d_out, int out_size)
{
    const float* x       = (const float*)d_in[0];
    const float* y       = (const float*)d_in[1];
    const int*   compost = (const int*)d_in[2];
    const int*   recycle = (const int*)d_in[3];
    const int*   donate  = (const int*)d_in[4];
    const int*   wl_map  = (const int*)d_in[5];

    fused_kernel<<<NB, TPB>>>(x, y,
                              compost, in_sizes[2],
                              recycle, in_sizes[3],
                              donate,  in_sizes[4],
                              wl_map,
                              (float*)d_out);
}

// round 6
// speedup vs baseline: 1.8021x; 1.8021x over previous
#include <cuda_runtime.h>
#include <cuda_bf16.h>
#include <cstdint>

// Problem constants (fixed by the dataset)
#define NB    2048
#define NC    9605
#define TPB   256
#define TOPK  10
#define NWARP (TPB / 32)

#define CLIP      0.05f
#define EPS_F     1e-8f
#define ALPHA1    2.0f
#define ALPHA_OTH 0.5f

// LUT config: piecewise-linear over x in [XMIN, XMIN + NBINS/BSCALE] = [-8, 8]
#define NBINS   1024
#define XMIN    (-8.0f)
#define BSCALE  64.0f            // bins per unit x

// top-k candidate collection
#define THRESH  2.5f             // 10th-largest of 9605 N(0,1) is ~3.05 sigma
#define WCAP    32               // slots per warp  (expected ~7.5 cands/warp)
#define XSLOT   (NWARP * WCAP)   // extra region base (lead/tail elements)
#define SLOTS   (XSLOT + 32)     // 288 total slots

__device__ float        g_row_sums[NB];
__device__ unsigned int g_count = 0;

__device__ __forceinline__ bool beats(float v, int i, float V, int I) {
    // jax.lax.top_k order: larger value first; ties -> lower index first
    return (v > V) || (v == V && i < I);
}

// exact base*w for a single element (used for LUT build, epilogue, fallback)
__device__ __forceinline__ float elem_term(float xv, float yv) {
    float e  = __expf(-xv);
    float p  = __fdividef(1.0f, 1.0f + e);          // sigmoid
    float xn = fminf(1.0f - p + CLIP, 1.0f);
    bool  pos = (yv != 0.0f);
    float arg  = pos ? p : xn;
    float onem = 1.0f - arg;
    float o2   = onem * onem;
    float w    = pos ? onem : (o2 * o2);             // gamma 1 vs 4
    return __logf(fmaxf(arg, EPS_F)) * w;
}

__device__ __forceinline__ void try_insert(float v, int i,
                                           float (&tv)[TOPK], int (&ti)[TOPK]) {
    if (beats(v, i, tv[TOPK-1], ti[TOPK-1])) {
        tv[TOPK-1] = v; ti[TOPK-1] = i;
        #pragma unroll
        for (int k = TOPK - 1; k > 0; k--) {
            if (beats(tv[k], ti[k], tv[k-1], ti[k-1])) {
                float fv = tv[k]; tv[k] = tv[k-1]; tv[k-1] = fv;
                int   iv = ti[k]; ti[k] = ti[k-1]; ti[k-1] = iv;
            }
        }
    }
}

__device__ __forceinline__ float lut_eval(const float2* __restrict__ tab, float xv) {
    float t = (xv - XMIN) * BSCALE;
    t = fminf(fmaxf(t, 0.0f), (float)NBINS - 0.001f);
    int   i = (int)t;
    float f = t - (float)i;
    float2 e = tab[i];
    return fmaf(f, e.y, e.x);
}

__global__ void __launch_bounds__(TPB)
fused_kernel(const float* __restrict__ x, const float* __restrict__ y,
             const int* __restrict__ compost, int n_compost,
             const int* __restrict__ recycle, int n_recycle,
             const int* __restrict__ donate,  int n_donate,
             const int* __restrict__ wl_map,
             float* __restrict__ out)
{
    const int row  = blockIdx.x;
    const int tid  = threadIdx.x;
    const int lane = tid & 31;
    const int wid  = tid >> 5;
    const float* __restrict__ xr = x + (long long)row * NC;
    const float* __restrict__ yr = y + (long long)row * NC;

    __shared__ float2 s_lutn[NBINS];
    __shared__ float2 s_lutp[NBINS];
    __shared__ float  s_grid[NBINS + 1];      // build scratch; reused for final reduce
    __shared__ float  s_cv[SLOTS];
    __shared__ int    s_ci[SLOTS];
    __shared__ float  s_wsum[NWARP];
    __shared__ int    s_wcnt[NWARP];
    __shared__ int    s_has[3];
    __shared__ float  s_topv[TOPK];
    __shared__ int    s_topi[TOPK];
    __shared__ int    s_extra;
    __shared__ int    s_islast;

    // ---------------- init + whitelist flags + LUT build ----------------
    if (tid < 3) s_has[tid] = 0;
    if (tid == 0) s_extra = 0;
    for (int i = tid; i < SLOTS; i += TPB) {
        s_cv[i] = __int_as_float(0xff800000);   // -inf
        s_ci[i] = 0x7fffffff;
    }

    for (int k = tid; k < n_compost; k += TPB)
        if (yr[compost[k]] != 0.0f) s_has[0] = 1;
    for (int k = tid; k < n_recycle; k += TPB)
        if (yr[recycle[k]] != 0.0f) s_has[1] = 1;
    for (int k = tid; k < n_donate; k += TPB)
        if (yr[donate[k]] != 0.0f) s_has[2] = 1;

    const float inv_scale = 1.0f / BSCALE;
    for (int i = tid; i <= NBINS; i += TPB)
        s_grid[i] = elem_term(XMIN + (float)i * inv_scale, 0.0f);
    __syncthreads();
    for (int i = tid; i < NBINS; i += TPB)
        s_lutn[i] = make_float2(s_grid[i], s_grid[i + 1] - s_grid[i]);
    __syncthreads();
    for (int i = tid; i <= NBINS; i += TPB)
        s_grid[i] = elem_term(XMIN + (float)i * inv_scale, 1.0f);
    __syncthreads();
    for (int i = tid; i < NBINS; i += TPB)
        s_lutp[i] = make_float2(s_grid[i], s_grid[i + 1] - s_grid[i]);
    __syncthreads();

    // ---------------- main pass: one read of x,y ----------------
    // Row alignment: (row*NC) % 4 == row % 4; `lead` scalars align the body.
    const int lead = (4 - (row & 3)) & 3;
    const int nb4  = (NC - lead) >> 2;
    const int tail = lead + (nb4 << 2);
    const float4* __restrict__ x4 = (const float4*)(xr + lead);
    const float4* __restrict__ y4 = (const float4*)(yr + lead);

    const unsigned lmask_lt = (1u << lane) - 1u;
    const int kmax = (nb4 + TPB - 1) / TPB;   // uniform trip count (ballot-safe)

    float sum   = 0.0f;
    int   wbase = 0;                           // per-warp candidate count (uniform)

    for (int k = 0; k < kmax; k++) {
        int  q  = tid + k * TPB;
        bool in = q < nb4;
        float4 xv, yv;
        if (in) { xv = x4[q]; yv = y4[q]; }
        else    { xv = make_float4(XMIN, XMIN, XMIN, XMIN);
                  yv = make_float4(0.f, 0.f, 0.f, 0.f); }   // contributes exactly 0
        int j = lead + (q << 2);

        #pragma unroll
        for (int s = 0; s < 4; s++) {
            float xs = (s == 0) ? xv.x : (s == 1) ? xv.y : (s == 2) ? xv.z : xv.w;
            float ys = (s == 0) ? yv.x : (s == 1) ? yv.y : (s == 2) ? yv.z : yv.w;
            const float2* tab = (ys != 0.0f) ? s_lutp : s_lutn;
            sum += lut_eval(tab, xs);

            bool pr = xs > THRESH;             // in==false -> xs==XMIN -> false
            unsigned m = __ballot_sync(0xffffffffu, pr);
            if (pr) {
                int p = wbase + __popc(m & lmask_lt);
                if (p < WCAP) {
                    s_cv[wid * WCAP + p] = xs;
                    s_ci[wid * WCAP + p] = j + s;
                }
            }
            wbase += __popc(m);
        }
    }

    // lead + tail scalars: handled by thread 0 (<=5 elements)
    if (tid == 0) {
        int ec = 0;
        for (int j = 0; j < lead; j++) {
            float xs = xr[j], ys = yr[j];
            sum += lut_eval((ys != 0.0f) ? s_lutp : s_lutn, xs);
            if (xs > THRESH) { s_cv[XSLOT + ec] = xs; s_ci[XSLOT + ec] = j; ec++; }
        }
        for (int j = tail; j < NC; j++) {
            float xs = xr[j], ys = yr[j];
            sum += lut_eval((ys != 0.0f) ? s_lutp : s_lutn, xs);
            if (xs > THRESH) { s_cv[XSLOT + ec] = xs; s_ci[XSLOT + ec] = j; ec++; }
        }
        s_extra = ec;
    }
    __syncwarp();

    // warp sum reduce
    #pragma unroll
    for (int off = 16; off >= 1; off >>= 1)
        sum += __shfl_down_sync(0xffffffffu, sum, off);
    if (lane == 0) { s_wsum[wid] = sum; s_wcnt[wid] = wbase; }
    __syncthreads();

    // ---------------- top-10 selection (warp 0) ----------------
    if (wid == 0) {
        int fb = 0;
        if (lane == 0) {
            int total = s_extra;
            #pragma unroll
            for (int w = 0; w < NWARP; w++) {
                int c = s_wcnt[w];
                if (c > WCAP) fb = 1;
                total += c;
            }
            if (total < TOPK) fb = 1;
        }
        fb = __shfl_sync(0xffffffffu, fb, 0);

        if (!fb) {
            // each lane owns SLOTS/32 = 9 slots
            float cv[SLOTS / 32];
            int   ci[SLOTS / 32];
            #pragma unroll
            for (int s = 0; s < SLOTS / 32; s++) {
                cv[s] = s_cv[lane + 32 * s];
                ci[s] = s_ci[lane + 32 * s];
            }
            for (int r = 0; r < TOPK; r++) {
                float bv = __int_as_float(0xff800000); int bi = 0x7fffffff; int bs = -1;
                #pragma unroll
                for (int s = 0; s < SLOTS / 32; s++)
                    if (beats(cv[s], ci[s], bv, bi)) { bv = cv[s]; bi = ci[s]; bs = s; }
                float mv = bv; int mi = bi;
                #pragma unroll
                for (int off = 16; off >= 1; off >>= 1) {
                    float ov = __shfl_down_sync(0xffffffffu, mv, off);
                    int   oi = __shfl_down_sync(0xffffffffu, mi, off);
                    if (beats(ov, oi, mv, mi)) { mv = ov; mi = oi; }
                }
                mv = __shfl_sync(0xffffffffu, mv, 0);
                mi = __shfl_sync(0xffffffffu, mi, 0);
                if (bs >= 0 && bi == mi && bv == mv)   // unique index -> one owner
                    cv[bs] = __int_as_float(0xff800000);
                if (lane == 0) { s_topv[r] = mv; s_topi[r] = mi; }
            }
        } else if (lane == 0) {
            // exact fallback (statistically never taken)
            float tv[TOPK]; int ti[TOPK];
            #pragma unroll
            for (int t = 0; t < TOPK; t++) { tv[t] = __int_as_float(0xff800000); ti[t] = 0x7fffffff; }
            for (int j = 0; j < NC; j++) try_insert(xr[j], j, tv, ti);
            #pragma unroll
            for (int t = 0; t < TOPK; t++) { s_topv[t] = tv[t]; s_topi[t] = ti[t]; }
        }
        __syncwarp();

        // ---------------- epilogue (lane 0) ----------------
        if (lane == 0) {
            bool has1 = s_has[0] != 0, has2 = s_has[1] != 0, has3 = s_has[2] != 0;
            bool gt_only4 = !(has1 || has2 || has3);
            bool found = false;
            float mults[TOPK];
            #pragma unroll
            for (int k = 0; k < TOPK; k++) {
                int j  = s_topi[k];
                int wl = wl_map[j];
                bool in_map = wl > 0;
                bool in_gt = ((wl == 1) && has1) || ((wl == 2) && has2) ||
                             ((wl == 3) && has3) || ((wl == 4) && gt_only4);
                float f = 1.0f;
                if (in_map && gt_only4)          f *= ALPHA_OTH;
                if (in_map && !in_gt && !found)  f *= ALPHA1;
                mults[k] = f;
                found = found || (in_map && in_gt);
            }
            float extra = found ? 1.0f : ALPHA1;
            float adj = 0.0f;
            #pragma unroll
            for (int k = 0; k < TOPK; k++) {
                float m = mults[k] * extra;
                if (m != 1.0f) {
                    int j = s_topi[k];
                    adj += elem_term(xr[j], yr[j]) * (m - 1.0f);
                }
            }
            float total = adj;
            #pragma unroll
            for (int w = 0; w < NWARP; w++) total += s_wsum[w];
            g_row_sums[row] = total;
            __threadfence();
            unsigned int old = atomicAdd(&g_count, 1u);
            s_islast = (old == NB - 1) ? 1 : 0;
        }
    }
    __syncthreads();

    // ---------------- last CTA folds the row sums (deterministic) --------
    if (s_islast) {
        __threadfence();
        float* s_red = s_grid;    // reuse scratch
        float s = 0.0f;
        for (int i = tid; i < NB; i += TPB) s += g_row_sums[i];
        s_red[tid] = s;
        __syncthreads();
        for (int st = TPB / 2; st >= 1; st >>= 1) {
            if (tid < st) s_red[tid] += s_red[tid + st];
            __syncthreads();
        }
        if (tid == 0) {
            out[0] = -s_red[0];
            g_count = 0;   // reset for next graph replay
        }
    }
}

extern "C" void kernel_launch(void* const* d_in, const int* in_sizes, int n_in,
                              void* d_out, int out_size)
{
    const float* x       = (const float*)d_in[0];
    const float* y       = (const float*)d_in[1];
    const int*   compost = (const int*)d_in[2];
    const int*   recycle = (const int*)d_in[3];
    const int*   donate  = (const int*)d_in[4];
    const int*   wl_map  = (const int*)d_in[5];

    fused_kernel<<<NB, TPB>>>(x, y,
                              compost, in_sizes[2],
                              recycle, in_sizes[3],
                              donate,  in_sizes[4],
                              wl_map,
                              (float*)d_out);
}

// round 9
// speedup vs baseline: 3.1814x; 1.7653x over previous
#include <cuda_runtime.h>
#include <cuda_bf16.h>
#include <cstdint>

// Problem constants (fixed by the dataset)
#define NB    2048
#define NC    9605
#define TPB   256
#define TOPK  10

#define CLIP      0.05f
#define EPS_F     1e-8f
#define ALPHA1    2.0f
#define ALPHA_OTH 0.5f

// LUT: piecewise-linear, slope-intercept vs global bin coordinate t
#define NBINS   1024
#define XMIN    (-8.0f)
#define BSCALE  64.0f               // bins per unit x ([-8,8] -> [0,1024))
#define TOFF    512.0f              // -XMIN*BSCALE

// candidate collection (top-10 of N(0,1) row is ~3.05 sigma; thresh 2.5 ->
// mean 59.6 candidates/row, P(<10) ~ 1e-15, P(>128) ~ 1e-17)
#define THRESH  2.5f
#define CAP     128

#define NCTA_A  2048
#define NQ      ((NB * NC) / 4)                    // 4,917,760 exact (no tail)
#define CHUNK   ((NQ + NCTA_A - 1) / NCTA_A)       // 2402 quads per CTA
#define NCTA_B  (NB / 8)                           // 256 CTAs, 1 warp per row

__device__ float        g_partials[NCTA_A];
__device__ int          g_cnt[NB];                 // zero-init; B resets
__device__ uint2        g_cand[NB * CAP];          // (value bits, col)
__device__ float        g_badj[NCTA_B];
__device__ unsigned int g_bdone = 0;

__device__ __forceinline__ bool beats(float v, int i, float V, int I) {
    // jax.lax.top_k order: larger value first; ties -> lower index first
    return (v > V) || (v == V && i < I);
}

// exact base*w for a single element (LUT build, epilogue, fallback)
__device__ __forceinline__ float elem_term(float xv, float yv) {
    float e  = __expf(-xv);
    float p  = __fdividef(1.0f, 1.0f + e);          // sigmoid
    float xn = fminf(1.0f - p + CLIP, 1.0f);
    bool  pos = (yv != 0.0f);
    float arg  = pos ? p : xn;
    float onem = 1.0f - arg;
    float o2   = onem * onem;
    float w    = pos ? onem : (o2 * o2);             // gamma 1 vs 4
    return __logf(fmaxf(arg, EPS_F)) * w;
}

__device__ __forceinline__ void try_insert(float v, int i,
                                           float (&tv)[TOPK], int (&ti)[TOPK]) {
    if (beats(v, i, tv[TOPK-1], ti[TOPK-1])) {
        tv[TOPK-1] = v; ti[TOPK-1] = i;
        #pragma unroll
        for (int k = TOPK - 1; k > 0; k--) {
            if (beats(tv[k], ti[k], tv[k-1], ti[k-1])) {
                float fv = tv[k]; tv[k] = tv[k-1]; tv[k-1] = fv;
                int   iv = ti[k]; ti[k] = ti[k-1]; ti[k-1] = iv;
            }
        }
    }
}

// ============================ Kernel A ==============================
// Flat streaming sum over the whole [NB*NC] array (aligned float4, no
// row logic) + rare candidate scatter to per-row global buckets.

struct LutPack { float c, s; };   // term = fma(t, s, c), t = global bin coord

__device__ __forceinline__ void accum_elem(const LutPack* __restrict__ lut,
                                           float xs, float ys, float& sum) {
    const LutPack* tab = (ys != 0.0f) ? lut + NBINS : lut;
    float t = fmaf(xs, BSCALE, TOFF);
    t = fminf(fmaxf(t, 0.0f), (float)NBINS - 0.01f);
    int i = (int)t;
    LutPack e = tab[i];
    sum += fmaf(t, e.s, e.c);
}

__device__ __forceinline__ void cand_elem(float xs, int j) {
    if (xs > THRESH) {
        int row = j / NC;                 // rare: compiler emits mul-hi magic
        int col = j - row * NC;
        int p = atomicAdd(&g_cnt[row], 1);
        if (p < CAP)
            g_cand[row * CAP + p] = make_uint2(__float_as_uint(xs), (unsigned)col);
    }
}

__device__ __forceinline__ void quad_body(const LutPack* __restrict__ lut,
                                          float4 xv, float4 yv, int q, float& sum) {
    accum_elem(lut, xv.x, yv.x, sum);
    accum_elem(lut, xv.y, yv.y, sum);
    accum_elem(lut, xv.z, yv.z, sum);
    accum_elem(lut, xv.w, yv.w, sum);
    float m = fmaxf(fmaxf(xv.x, xv.y), fmaxf(xv.z, xv.w));
    if (m > THRESH) {                      // ~0.55 of warp-quads enter; lanes rare
        int j = q << 2;
        cand_elem(xv.x, j + 0);
        cand_elem(xv.y, j + 1);
        cand_elem(xv.z, j + 2);
        cand_elem(xv.w, j + 3);
    }
}

__global__ void __launch_bounds__(TPB)
stream_kernel(const float* __restrict__ x, const float* __restrict__ y)
{
    __shared__ LutPack s_lut[2 * NBINS];
    __shared__ float   s_red[TPB / 32];

    const int tid  = threadIdx.x;
    const int lane = tid & 31;
    const int wid  = tid >> 5;

    // build both LUTs (16 exact evals per thread; ~400 cyc, amortized)
    const float h = 1.0f / BSCALE;
    for (int e = tid; e < 2 * NBINS; e += TPB) {
        int  b   = e & (NBINS - 1);
        float yv = (e >= NBINS) ? 1.0f : 0.0f;
        float x0 = XMIN + (float)b * h;
        float v0 = elem_term(x0, yv);
        float v1 = elem_term(x0 + h, yv);
        float sl = v1 - v0;
        s_lut[e].c = v0 - sl * (float)b;
        s_lut[e].s = sl;
    }
    __syncthreads();

    const float4* __restrict__ x4 = (const float4*)x;
    const float4* __restrict__ y4 = (const float4*)y;

    const int base = blockIdx.x * CHUNK;
    const int qend = min(base + CHUNK, NQ);

    float sum = 0.0f;
    int q = base + tid;
    for (; q + TPB < qend; q += 2 * TPB) {
        float4 xa = x4[q];        float4 ya = y4[q];
        float4 xb = x4[q + TPB];  float4 yb = y4[q + TPB];
        quad_body(s_lut, xa, ya, q,       sum);
        quad_body(s_lut, xb, yb, q + TPB, sum);
    }
    for (; q < qend; q += TPB) {
        float4 xa = x4[q]; float4 ya = y4[q];
        quad_body(s_lut, xa, ya, q, sum);
    }

    #pragma unroll
    for (int off = 16; off >= 1; off >>= 1)
        sum += __shfl_down_sync(0xffffffffu, sum, off);
    if (lane == 0) s_red[wid] = sum;
    __syncthreads();
    if (tid == 0) {
        float t = 0.0f;
        #pragma unroll
        for (int w = 0; w < TPB / 32; w++) t += s_red[w];
        g_partials[blockIdx.x] = t;
    }
}

// ============================ Kernel B ==============================
// One warp per row: top-10 from candidate bucket, whitelist flags,
// exact adjustment. Last CTA folds everything into the scalar output.

__global__ void __launch_bounds__(TPB)
row_kernel(const float* __restrict__ x, const float* __restrict__ y,
           const int* __restrict__ compost, int n_compost,
           const int* __restrict__ recycle, int n_recycle,
           const int* __restrict__ donate,  int n_donate,
           const int* __restrict__ wl_map,
           float* __restrict__ out)
{
    const int tid  = threadIdx.x;
    const int lane = tid & 31;
    const int wid  = tid >> 5;
    const int row  = blockIdx.x * (TPB / 32) + wid;

    __shared__ float s_adj[TPB / 32];
    __shared__ int   s_islast;

    const float* __restrict__ xr = x + (long long)row * NC;
    const float* __restrict__ yr = y + (long long)row * NC;

    // whitelist group flags (lane-parallel gathers)
    int f1 = 0, f2 = 0, f3 = 0;
    for (int k = lane; k < n_compost; k += 32) f1 |= (yr[compost[k]] != 0.0f);
    for (int k = lane; k < n_recycle; k += 32) f2 |= (yr[recycle[k]] != 0.0f);
    for (int k = lane; k < n_donate;  k += 32) f3 |= (yr[donate[k]]  != 0.0f);
    bool has1 = __any_sync(0xffffffffu, f1);
    bool has2 = __any_sync(0xffffffffu, f2);
    bool has3 = __any_sync(0xffffffffu, f3);

    // ---- top-10 ----
    int cnt = g_cnt[row];
    bool fb = (cnt > CAP) || (cnt < TOPK);

    float tv[TOPK]; int ti[TOPK];
    if (!fb) {
        const uint2* __restrict__ bucket = g_cand + row * CAP;
        float cv[CAP / 32]; int ci[CAP / 32];
        #pragma unroll
        for (int s = 0; s < CAP / 32; s++) {
            int k = lane + 32 * s;
            if (k < cnt) {
                uint2 c = bucket[k];
                cv[s] = __uint_as_float(c.x);
                ci[s] = (int)c.y;
            } else {
                cv[s] = __int_as_float(0xff800000);
                ci[s] = 0x7fffffff;
            }
        }
        #pragma unroll
        for (int r = 0; r < TOPK; r++) {
            float bv = __int_as_float(0xff800000); int bi = 0x7fffffff; int bs = -1;
            #pragma unroll
            for (int s = 0; s < CAP / 32; s++)
                if (beats(cv[s], ci[s], bv, bi)) { bv = cv[s]; bi = ci[s]; bs = s; }
            float mv = bv; int mi = bi;
            #pragma unroll
            for (int off = 16; off >= 1; off >>= 1) {
                float ov = __shfl_down_sync(0xffffffffu, mv, off);
                int   oi = __shfl_down_sync(0xffffffffu, mi, off);
                if (beats(ov, oi, mv, mi)) { mv = ov; mi = oi; }
            }
            mv = __shfl_sync(0xffffffffu, mv, 0);
            mi = __shfl_sync(0xffffffffu, mi, 0);
            if (bs >= 0 && bv == mv && bi == mi)   // unique index -> one owner
                cv[bs] = __int_as_float(0xff800000);
            tv[r] = mv; ti[r] = mi;
        }
    } else if (lane == 0) {
        // exact fallback (statistically never taken)
        #pragma unroll
        for (int t = 0; t < TOPK; t++) { tv[t] = __int_as_float(0xff800000); ti[t] = 0x7fffffff; }
        for (int j = 0; j < NC; j++) try_insert(xr[j], j, tv, ti);
    }

    // ---- epilogue on lane 0 ----
    if (lane == 0) {
        bool gt_only4 = !(has1 || has2 || has3);
        bool found = false;
        float mults[TOPK];
        #pragma unroll
        for (int k = 0; k < TOPK; k++) {
            int j  = ti[k];
            int wl = wl_map[j];
            bool in_map = wl > 0;
            bool in_gt = ((wl == 1) && has1) || ((wl == 2) && has2) ||
                         ((wl == 3) && has3) || ((wl == 4) && gt_only4);
            float f = 1.0f;
            if (in_map && gt_only4)          f *= ALPHA_OTH;
            if (in_map && !in_gt && !found)  f *= ALPHA1;
            mults[k] = f;
            found = found || (in_map && in_gt);
        }
        float extra = found ? 1.0f : ALPHA1;
        float adj = 0.0f;
        #pragma unroll
        for (int k = 0; k < TOPK; k++) {
            float m = mults[k] * extra;
            if (m != 1.0f) {
                int j = ti[k];
                adj += elem_term(xr[j], yr[j]) * (m - 1.0f);
            }
        }
        s_adj[wid] = adj;
        g_cnt[row] = 0;                 // reset bucket for next graph replay
    }
    __syncthreads();

    if (tid == 0) {
        float b = 0.0f;
        #pragma unroll
        for (int w = 0; w < TPB / 32; w++) b += s_adj[w];
        g_badj[blockIdx.x] = b;
        __threadfence();
        unsigned int old = atomicAdd(&g_bdone, 1u);
        s_islast = (old == NCTA_B - 1) ? 1 : 0;
    }
    __syncthreads();

    // ---- last CTA: fold partials + adjustments (deterministic order) ----
    if (s_islast) {
        __threadfence();
        __shared__ float s_red[TPB];
        float s = 0.0f;
        for (int i = tid; i < NCTA_A; i += TPB) s += g_partials[i];
        for (int i = tid; i < NCTA_B; i += TPB) s += g_badj[i];
        s_red[tid] = s;
        __syncthreads();
        for (int st = TPB / 2; st >= 1; st >>= 1) {
            if (tid < st) s_red[tid] += s_red[tid + st];
            __syncthreads();
        }
        if (tid == 0) {
            out[0] = -s_red[0];
            g_bdone = 0;               // reset for next graph replay
        }
    }
}

extern "C" void kernel_launch(void* const* d_in, const int* in_sizes, int n_in,
                              void* d_out, int out_size)
{
    const float* x       = (const float*)d_in[0];
    const float* y       = (const float*)d_in[1];
    const int*   compost = (const int*)d_in[2];
    const int*   recycle = (const int*)d_in[3];
    const int*   donate  = (const int*)d_in[4];
    const int*   wl_map  = (const int*)d_in[5];

    stream_kernel<<<NCTA_A, TPB>>>(x, y);
    row_kernel<<<NCTA_B, TPB>>>(x, y,
                                compost, in_sizes[2],
                                recycle, in_sizes[3],
                                donate,  in_sizes[4],
                                wl_map,
                                (float*)d_out);
}

// round 10
// speedup vs baseline: 3.6375x; 1.1434x over previous
#include <cuda_runtime.h>
#include <cuda_bf16.h>
#include <cstdint>

// Problem constants (fixed by the dataset)
#define NB    2048
#define NC    9605
#define TPB   256
#define TOPK  10
#define NROW  4                       // rows per CTA
#define NCTA  (NB / NROW)             // 512
#define QPC   ((NROW * NC) / 4)       // 9605 quads per CTA (exact)

#define CLIP      0.05f
#define EPS_F     1e-8f
#define ALPHA1    2.0f
#define ALPHA_OTH 0.5f

// LUT: piecewise-linear, slope-intercept vs global bin coordinate t
#define NBINS   1024
#define XMIN    (-8.0f)
#define BSCALE  64.0f                 // bins per unit x ([-8,8] -> [0,1024))
#define TOFF    512.0f                // -XMIN*BSCALE

// candidate collection (row 10th-max of N(0,1) is ~3.05 sigma; thresh 2.5 ->
// ~60 candidates/row, P(<10) ~1e-15, P(>128) ~1e-17; fallback guards both)
#define THRESH  2.5f
#define CAP     128
#define YFLAG   (1 << 16)             // packed y!=0 flag in candidate index
#define CMASK   0xFFFF

__device__ float        g_partials[NCTA];
__device__ unsigned int g_done = 0;

__device__ __forceinline__ bool beatsP(float v, int i, float V, int I) {
    // jax.lax.top_k order: larger value first; ties -> lower col first
    return (v > V) || (v == V && (i & CMASK) < (I & CMASK));
}

// exact base*w for a single element (LUT build, epilogue, fallback)
__device__ __forceinline__ float elem_term(float xv, float yv) {
    float e  = __expf(-xv);
    float p  = __fdividef(1.0f, 1.0f + e);          // sigmoid
    float xn = fminf(1.0f - p + CLIP, 1.0f);
    bool  pos = (yv != 0.0f);
    float arg  = pos ? p : xn;
    float onem = 1.0f - arg;
    float o2   = onem * onem;
    float w    = pos ? onem : (o2 * o2);             // gamma 1 vs 4
    return __logf(fmaxf(arg, EPS_F)) * w;
}

struct LutPack { float c, s; };   // term = fma(t, s, c), t = global bin coord

__global__ void __launch_bounds__(TPB)
fused_kernel(const float* __restrict__ x, const float* __restrict__ y,
             const int* __restrict__ compost, int n_compost,
             const int* __restrict__ recycle, int n_recycle,
             const int* __restrict__ donate,  int n_donate,
             const int* __restrict__ wl_map,
             float* __restrict__ out)
{
    __shared__ LutPack s_lut[2 * NBINS];            // 16 KB (reused for final fold)
    __shared__ float   s_cv[NROW][CAP];
    __shared__ int     s_ci[NROW][CAP];
    __shared__ int     s_cnt[NROW];
    __shared__ int     s_has[NROW][3];
    __shared__ float   s_wsum[TPB / 32];
    __shared__ float   s_adj[NROW];
    __shared__ int     s_islast;

    const int tid  = threadIdx.x;
    const int lane = tid & 31;
    const int wid  = tid >> 5;
    const int cta  = blockIdx.x;
    const long long ebase = (long long)cta * (NROW * NC);

    // ---- init shared ----
    if (tid < NROW) { s_cnt[tid] = 0; s_adj[tid] = 0.0f; }
    if (tid < NROW * 3) s_has[tid >> 2][tid & 3 ? (tid & 3) - 1 : 0] = 0; // overwritten below
    if (tid < 12) ((int*)s_has)[tid] = 0;
    __syncthreads();   // s_has zero before gather stores

    // ---- whitelist-flag gathers (issued early; latency hidden by LUT build) ----
    #pragma unroll
    for (int r = 0; r < NROW; r++) {
        const float* __restrict__ yr = y + ebase + (long long)r * NC;
        for (int k = tid; k < n_compost; k += TPB)
            if (yr[compost[k]] != 0.0f) atomicOr(&s_has[r][0], 1);
        for (int k = tid; k < n_recycle; k += TPB)
            if (yr[recycle[k]] != 0.0f) atomicOr(&s_has[r][1], 1);
        for (int k = tid; k < n_donate;  k += TPB)
            if (yr[donate[k]]  != 0.0f) atomicOr(&s_has[r][2], 1);
    }

    // ---- build both LUTs (MUFU-heavy; overlaps the gathers above) ----
    const float h = 1.0f / BSCALE;
    for (int e = tid; e < 2 * NBINS; e += TPB) {
        int   b  = e & (NBINS - 1);
        float yv = (e >= NBINS) ? 1.0f : 0.0f;
        float x0 = XMIN + (float)b * h;
        float v0 = elem_term(x0, yv);
        float v1 = elem_term(x0 + h, yv);
        float sl = v1 - v0;
        s_lut[e].c = v0 - sl * (float)b;
        s_lut[e].s = sl;
    }
    __syncthreads();

    // ---- main streaming pass over this CTA's 4 rows ----
    const float4* __restrict__ x4 = (const float4*)(x + ebase);
    const float4* __restrict__ y4 = (const float4*)(y + ebase);

    float sum = 0.0f;

    auto accum = [&](float xs, float ys) {
        const LutPack* tab = (ys != 0.0f) ? s_lut + NBINS : s_lut;
        float t = fmaf(xs, BSCALE, TOFF);
        t = fminf(fmaxf(t, 0.0f), (float)NBINS - 0.01f);
        int i = (int)t;
        LutPack e = tab[i];
        sum += fmaf(t, e.s, e.c);
    };
    auto cand = [&](float xs, float ys, int e) {
        if (xs > THRESH) {
            int r   = (e >= 2 * NC) ? ((e >= 3 * NC) ? 3 : 2)
                                    : ((e >= NC) ? 1 : 0);
            int col = e - r * NC;
            int p = atomicAdd(&s_cnt[r], 1);
            if (p < CAP) {
                s_cv[r][p] = xs;
                s_ci[r][p] = col | ((ys != 0.0f) ? YFLAG : 0);
            }
        }
    };
    auto quad = [&](float4 xv, float4 yv, int q) {
        accum(xv.x, yv.x); accum(xv.y, yv.y);
        accum(xv.z, yv.z); accum(xv.w, yv.w);
        float m = fmaxf(fmaxf(xv.x, xv.y), fmaxf(xv.z, xv.w));
        if (m > THRESH) {
            int e = q << 2;
            cand(xv.x, yv.x, e + 0); cand(xv.y, yv.y, e + 1);
            cand(xv.z, yv.z, e + 2); cand(xv.w, yv.w, e + 3);
        }
    };

    int q = tid;
    for (; q + TPB < QPC; q += 2 * TPB) {
        float4 xa = x4[q];        float4 ya = y4[q];
        float4 xb = x4[q + TPB];  float4 yb = y4[q + TPB];
        quad(xa, ya, q);
        quad(xb, yb, q + TPB);
    }
    for (; q < QPC; q += TPB) {
        float4 xa = x4[q]; float4 ya = y4[q];
        quad(xa, ya, q);
    }

    // block sum reduce
    #pragma unroll
    for (int off = 16; off >= 1; off >>= 1)
        sum += __shfl_down_sync(0xffffffffu, sum, off);
    if (lane == 0) s_wsum[wid] = sum;
    __syncthreads();   // candidates + flags + wsums all visible

    // ---- per-row top-10 + whitelist epilogue: warp r handles row r ----
    if (wid < NROW) {
        const int r = wid;
        int cnt = s_cnt[r];
        bool fb = (cnt > CAP) || (cnt < TOPK);

        float tv[TOPK]; int ti[TOPK];
        if (!fb) {
            float cv[CAP / 32]; int ci[CAP / 32];
            #pragma unroll
            for (int s = 0; s < CAP / 32; s++) {
                int k = lane + 32 * s;
                if (k < cnt) { cv[s] = s_cv[r][k]; ci[s] = s_ci[r][k]; }
                else         { cv[s] = __int_as_float(0xff800000); ci[s] = CMASK; }
            }
            #pragma unroll
            for (int rr = 0; rr < TOPK; rr++) {
                float bv = __int_as_float(0xff800000); int bi = CMASK; int bs = -1;
                #pragma unroll
                for (int s = 0; s < CAP / 32; s++)
                    if (beatsP(cv[s], ci[s], bv, bi)) { bv = cv[s]; bi = ci[s]; bs = s; }
                float mv = bv; int mi = bi;
                #pragma unroll
                for (int off = 16; off >= 1; off >>= 1) {
                    float ov = __shfl_down_sync(0xffffffffu, mv, off);
                    int   oi = __shfl_down_sync(0xffffffffu, mi, off);
                    if (beatsP(ov, oi, mv, mi)) { mv = ov; mi = oi; }
                }
                mv = __shfl_sync(0xffffffffu, mv, 0);
                mi = __shfl_sync(0xffffffffu, mi, 0);
                if (bs >= 0 && bv == mv && bi == mi)   // unique col -> one owner
                    cv[bs] = __int_as_float(0xff800000);
                tv[rr] = mv; ti[rr] = mi;
            }
        } else if (lane == 0) {
            // exact fallback (statistically never taken)
            const float* __restrict__ xr = x + ebase + (long long)r * NC;
            const float* __restrict__ yr = y + ebase + (long long)r * NC;
            #pragma unroll
            for (int t = 0; t < TOPK; t++) { tv[t] = __int_as_float(0xff800000); ti[t] = CMASK; }
            for (int j = 0; j < NC; j++) {
                float v = xr[j];
                if (beatsP(v, j, tv[TOPK-1], ti[TOPK-1])) {
                    tv[TOPK-1] = v; ti[TOPK-1] = j;
                    #pragma unroll
                    for (int k2 = TOPK - 1; k2 > 0; k2--) {
                        if (beatsP(tv[k2], ti[k2], tv[k2-1], ti[k2-1])) {
                            float fv = tv[k2]; tv[k2] = tv[k2-1]; tv[k2-1] = fv;
                            int   iv = ti[k2]; ti[k2] = ti[k2-1]; ti[k2-1] = iv;
                        }
                    }
                }
            }
            #pragma unroll
            for (int t = 0; t < TOPK; t++)
                if (yr[ti[t] & CMASK] != 0.0f) ti[t] |= YFLAG;
        }

        if (lane == 0) {
            bool has1 = s_has[r][0] != 0, has2 = s_has[r][1] != 0, has3 = s_has[r][2] != 0;
            bool gt_only4 = !(has1 || has2 || has3);
            bool found = false;
            float mults[TOPK];
            #pragma unroll
            for (int k = 0; k < TOPK; k++) {
                int wl = wl_map[ti[k] & CMASK];
                bool in_map = wl > 0;
                bool in_gt = ((wl == 1) && has1) || ((wl == 2) && has2) ||
                             ((wl == 3) && has3) || ((wl == 4) && gt_only4);
                float f = 1.0f;
                if (in_map && gt_only4)          f *= ALPHA_OTH;
                if (in_map && !in_gt && !found)  f *= ALPHA1;
                mults[k] = f;
                found = found || (in_map && in_gt);
            }
            float extra = found ? 1.0f : ALPHA1;
            float adj = 0.0f;
            #pragma unroll
            for (int k = 0; k < TOPK; k++) {
                float m = mults[k] * extra;
                if (m != 1.0f)
                    adj += elem_term(tv[k], (ti[k] & YFLAG) ? 1.0f : 0.0f) * (m - 1.0f);
            }
            s_adj[r] = adj;
        }
    }
    __syncthreads();

    if (tid == 0) {
        float t = 0.0f;
        #pragma unroll
        for (int w = 0; w < TPB / 32; w++) t += s_wsum[w];
        #pragma unroll
        for (int r = 0; r < NROW; r++) t += s_adj[r];
        g_partials[cta] = t;
        __threadfence();
        unsigned int old = atomicAdd(&g_done, 1u);
        s_islast = (old == NCTA - 1) ? 1 : 0;
    }
    __syncthreads();

    // ---- last CTA: fold all partials (deterministic fixed order) ----
    if (s_islast) {
        __threadfence();
        float* s_red = (float*)s_lut;   // LUT no longer needed
        float s = 0.0f;
        for (int i = tid; i < NCTA; i += TPB) s += g_partials[i];
        s_red[tid] = s;
        __syncthreads();
        for (int st = TPB / 2; st >= 1; st >>= 1) {
            if (tid < st) s_red[tid] += s_red[tid + st];
            __syncthreads();
        }
        if (tid == 0) {
            out[0] = -s_red[0];
            g_done = 0;                 // reset for next graph replay
        }
    }
}

extern "C" void kernel_launch(void* const* d_in, const int* in_sizes, int n_in,
                              void* d_out, int out_size)
{
    const float* x       = (const float*)d_in[0];
    const float* y       = (const float*)d_in[1];
    const int*   compost = (const int*)d_in[2];
    const int*   recycle = (const int*)d_in[3];
    const int*   donate  = (const int*)d_in[4];
    const int*   wl_map  = (const int*)d_in[5];

    fused_kernel<<<NCTA, TPB>>>(x, y,
                                compost, in_sizes[2],
                                recycle, in_sizes[3],
                                donate,  in_sizes[4],
                                wl_map,
                                (float*)d_out);
}